// round 1
// baseline (speedup 1.0000x reference)
#include <cuda_runtime.h>

// ---------------------------------------------------------------------------
// PixelCrossAttention2D: out = sigmoid(YK @ XQ^T) @ YK + XQ
//   XQ = x @ W1 + b1, YK = y @ W2 + b2   (per-pixel 1x1 convs)
// Shapes: B=4, HW=4096, C=NF=128, all fp32.
// Round 0: fp32 SIMT baseline (guaranteed-accurate), compute-bound on FFMA.
// ---------------------------------------------------------------------------

constexpr int kB   = 4;
constexpr int kHW  = 4096;
constexpr int kC   = 128;
constexpr int kNF  = 128;

// smem row stride (floats) for 128-wide tiles: 132 keeps float4 alignment and
// makes row-strided accesses land on distinct banks (4*m mod 32 distinct for
// the 8 distinct rows touched per warp).
constexpr int RS   = 132;
constexpr int ATTN_SMEM_BYTES = 3 * 64 * RS * 4;   // yki + xqj + ykj tiles

// A (post-sigmoid) tile row stride inside the recycled xqj buffer.
constexpr int AS   = 68;

// Scratch for projected tensors (allocation-free rule: __device__ globals).
__device__ float g_xq[kB * kHW * kNF];
__device__ float g_yk[kB * kHW * kNF];

// ---------------------------------------------------------------------------
// Projection: out[p, f] = sum_c in[p, c] * W[c, f] + bias[f]
// grid = (256 pixel-tiles of 64 rows, 2 which), block = 256
// ---------------------------------------------------------------------------
__global__ __launch_bounds__(256) void proj_kernel(
    const float* __restrict__ x,  const float* __restrict__ y,
    const float* __restrict__ W1, const float* __restrict__ b1,
    const float* __restrict__ W2, const float* __restrict__ b2)
{
    __shared__ float  xs[64][129];      // input rows, pad 129 -> conflict-free column reads
    __shared__ float4 ws[16][32];       // W chunk: 16 c-rows x 128 f (as 32 float4)

    const int which = blockIdx.y;
    const float* in   = which ? y  : x;
    const float* W    = which ? W2 : W1;
    const float* bias = which ? b2 : b1;
    float* out        = which ? g_yk : g_xq;

    const int base = blockIdx.x * 64;   // pixel row base in [0, B*HW)
    const int t    = threadIdx.x;
    const int row  = t & 63;            // warp = 32 consecutive rows, same fgrp
    const int fgrp = t >> 6;            // 0..3
    const int f0   = fgrp * 32;

    // Load 64x128 input rows (coalesced float4).
    for (int v = t; v < 64 * 32; v += 256) {
        int r = v >> 5, c4 = v & 31;
        float4 d = reinterpret_cast<const float4*>(in + (long)(base + r) * kC)[c4];
        xs[r][c4 * 4 + 0] = d.x; xs[r][c4 * 4 + 1] = d.y;
        xs[r][c4 * 4 + 2] = d.z; xs[r][c4 * 4 + 3] = d.w;
    }

    float acc[32];
    #pragma unroll
    for (int i = 0; i < 32; i++) acc[i] = bias[f0 + i];

    for (int c0 = 0; c0 < kC; c0 += 16) {
        __syncthreads();   // guards xs (first iter) and ws rewrite (later iters)
        for (int v = t; v < 16 * 32; v += 256) {
            int r = v >> 5, c4 = v & 31;
            ws[r][c4] = reinterpret_cast<const float4*>(W + (long)(c0 + r) * kNF)[c4];
        }
        __syncthreads();
        #pragma unroll
        for (int cc = 0; cc < 16; cc++) {
            float xv = xs[row][c0 + cc];
            #pragma unroll
            for (int q = 0; q < 8; q++) {
                float4 w = ws[cc][fgrp * 8 + q];   // same addr across warp -> broadcast
                acc[q * 4 + 0] += xv * w.x;
                acc[q * 4 + 1] += xv * w.y;
                acc[q * 4 + 2] += xv * w.z;
                acc[q * 4 + 3] += xv * w.w;
            }
        }
    }

    float* o = out + (long)(base + row) * kNF + f0;
    #pragma unroll
    for (int q = 0; q < 8; q++) {
        float4 d = make_float4(acc[q * 4 + 0], acc[q * 4 + 1],
                               acc[q * 4 + 2], acc[q * 4 + 3]);
        reinterpret_cast<float4*>(o)[q] = d;
    }
}

// ---------------------------------------------------------------------------
// Attention: per CTA one 64-row query tile (yk_i), stream 64-wide j tiles.
//   S[m][j] = sum_c yki[m][c] * xqj[j][c]   -> sigmoid -> A
//   O[m][n] += sum_k A[m][k] * ykj[k][n]
// Thread grid 16x16: m = ty*4+i (4 rows), j = tx+16u (4 cols, strided),
// PV cols n = tx*4+e and 64+tx*4+e (8 cols). O register-resident (32/thread).
// grid = (64 i-tiles, 4 batches), block = 256, occupancy 2 -> 1 full wave.
// ---------------------------------------------------------------------------
__global__ __launch_bounds__(256, 2) void attn_kernel(float* __restrict__ out)
{
    extern __shared__ float smem[];
    float* s_yki = smem;                 // [64][RS]
    float* s_xqj = smem + 64 * RS;       // [64][RS]; recycled as A [64][AS]
    float* s_ykj = smem + 2 * 64 * RS;   // [64][RS]

    const int b  = blockIdx.y;
    const int i0 = blockIdx.x * 64;
    const int t  = threadIdx.x;
    const int ty = t >> 4;               // 0..15
    const int tx = t & 15;               // 0..15
    const long bbase = (long)b * kHW * kNF;

    // Load resident query tile yk_i.
    for (int v = t; v < 64 * 32; v += 256) {
        int r = v >> 5, c4 = v & 31;
        float4 d = reinterpret_cast<const float4*>(g_yk + bbase + (long)(i0 + r) * kNF)[c4];
        *reinterpret_cast<float4*>(&s_yki[r * RS + c4 * 4]) = d;
    }

    float O[4][8];
    #pragma unroll
    for (int i = 0; i < 4; i++)
        #pragma unroll
        for (int n = 0; n < 8; n++) O[i][n] = 0.f;

    for (int j0 = 0; j0 < kHW; j0 += 64) {
        __syncthreads();   // previous PV reads of A/ykj done (also guards yki load, iter 0)

        for (int v = t; v < 64 * 32; v += 256) {
            int r = v >> 5, c4 = v & 31;
            *reinterpret_cast<float4*>(&s_xqj[r * RS + c4 * 4]) =
                reinterpret_cast<const float4*>(g_xq + bbase + (long)(j0 + r) * kNF)[c4];
            *reinterpret_cast<float4*>(&s_ykj[r * RS + c4 * 4]) =
                reinterpret_cast<const float4*>(g_yk + bbase + (long)(j0 + r) * kNF)[c4];
        }
        __syncthreads();

        // ---- S = yki @ xqj^T ----
        float S[4][4];
        #pragma unroll
        for (int i = 0; i < 4; i++)
            #pragma unroll
            for (int u = 0; u < 4; u++) S[i][u] = 0.f;

        #pragma unroll 1
        for (int c4 = 0; c4 < 32; c4++) {
            float4 a[4], q[4];
            #pragma unroll
            for (int i = 0; i < 4; i++)
                a[i] = *reinterpret_cast<const float4*>(&s_yki[(ty * 4 + i) * RS + c4 * 4]);
            #pragma unroll
            for (int u = 0; u < 4; u++)
                q[u] = *reinterpret_cast<const float4*>(&s_xqj[(tx + 16 * u) * RS + c4 * 4]);
            #pragma unroll
            for (int i = 0; i < 4; i++)
                #pragma unroll
                for (int u = 0; u < 4; u++) {
                    S[i][u] += a[i].x * q[u].x;
                    S[i][u] += a[i].y * q[u].y;
                    S[i][u] += a[i].z * q[u].z;
                    S[i][u] += a[i].w * q[u].w;
                }
        }
        __syncthreads();   // all reads of xqj done before recycling it for A

        // ---- sigmoid, stage A in recycled xqj buffer ----
        #pragma unroll
        for (int i = 0; i < 4; i++)
            #pragma unroll
            for (int u = 0; u < 4; u++) {
                float aval = __fdividef(1.f, 1.f + __expf(-S[i][u]));
                s_xqj[(ty * 4 + i) * AS + (tx + 16 * u)] = aval;
            }
        __syncthreads();

        // ---- O += A @ ykj ----
        #pragma unroll 4
        for (int k = 0; k < 64; k++) {
            float av[4];
            #pragma unroll
            for (int i = 0; i < 4; i++)
                av[i] = s_xqj[(ty * 4 + i) * AS + k];   // broadcast across tx
            float4 w0 = *reinterpret_cast<const float4*>(&s_ykj[k * RS + tx * 4]);
            float4 w1 = *reinterpret_cast<const float4*>(&s_ykj[k * RS + 64 + tx * 4]);
            #pragma unroll
            for (int i = 0; i < 4; i++) {
                O[i][0] += av[i] * w0.x;  O[i][1] += av[i] * w0.y;
                O[i][2] += av[i] * w0.z;  O[i][3] += av[i] * w0.w;
                O[i][4] += av[i] * w1.x;  O[i][5] += av[i] * w1.y;
                O[i][6] += av[i] * w1.z;  O[i][7] += av[i] * w1.w;
            }
        }
    }

    // ---- epilogue: out = O + XQ ----
    #pragma unroll
    for (int i = 0; i < 4; i++) {
        long rowoff = bbase + (long)(i0 + ty * 4 + i) * kNF;
        float4 q0 = *reinterpret_cast<const float4*>(g_xq + rowoff + tx * 4);
        float4 q1 = *reinterpret_cast<const float4*>(g_xq + rowoff + 64 + tx * 4);
        float4 r0 = make_float4(O[i][0] + q0.x, O[i][1] + q0.y,
                                O[i][2] + q0.z, O[i][3] + q0.w);
        float4 r1 = make_float4(O[i][4] + q1.x, O[i][5] + q1.y,
                                O[i][6] + q1.z, O[i][7] + q1.w);
        *reinterpret_cast<float4*>(out + rowoff + tx * 4) = r0;
        *reinterpret_cast<float4*>(out + rowoff + 64 + tx * 4) = r1;
    }
}

// ---------------------------------------------------------------------------
extern "C" void kernel_launch(void* const* d_in, const int* in_sizes, int n_in,
                              void* d_out, int out_size)
{
    const float* x  = (const float*)d_in[0];
    const float* y  = (const float*)d_in[1];
    const float* W1 = (const float*)d_in[2];
    const float* b1 = (const float*)d_in[3];
    const float* W2 = (const float*)d_in[4];
    const float* b2 = (const float*)d_in[5];

    cudaFuncSetAttribute(attn_kernel, cudaFuncAttributeMaxDynamicSharedMemorySize,
                         ATTN_SMEM_BYTES);

    proj_kernel<<<dim3(256, 2), 256>>>(x, y, W1, b1, W2, b2);
    attn_kernel<<<dim3(64, 4), 256, ATTN_SMEM_BYTES>>>((float*)d_out);
}

// round 2
// speedup vs baseline: 1.0031x; 1.0031x over previous
#include <cuda_runtime.h>

// ---------------------------------------------------------------------------
// PixelCrossAttention2D: out = sigmoid(YK @ XQ^T) @ YK + XQ
//   XQ = x @ W1 + b1, YK = y @ W2 + b2   (per-pixel 1x1 convs)
// Shapes: B=4, HW=4096, C=NF=128, all fp32.
// Round 0: fp32 SIMT baseline (guaranteed-accurate), compute-bound on FFMA.
// ---------------------------------------------------------------------------

constexpr int kB   = 4;
constexpr int kHW  = 4096;
constexpr int kC   = 128;
constexpr int kNF  = 128;

// smem row stride (floats) for 128-wide tiles: 132 keeps float4 alignment and
// makes row-strided accesses land on distinct banks (4*m mod 32 distinct for
// the 8 distinct rows touched per warp).
constexpr int RS   = 132;
constexpr int ATTN_SMEM_BYTES = 3 * 64 * RS * 4;   // yki + xqj + ykj tiles

// A (post-sigmoid) tile row stride inside the recycled xqj buffer.
constexpr int AS   = 68;

// Scratch for projected tensors (allocation-free rule: __device__ globals).
__device__ float g_xq[kB * kHW * kNF];
__device__ float g_yk[kB * kHW * kNF];

// ---------------------------------------------------------------------------
// Projection: out[p, f] = sum_c in[p, c] * W[c, f] + bias[f]
// grid = (256 pixel-tiles of 64 rows, 2 which), block = 256
// ---------------------------------------------------------------------------
__global__ __launch_bounds__(256) void proj_kernel(
    const float* __restrict__ x,  const float* __restrict__ y,
    const float* __restrict__ W1, const float* __restrict__ b1,
    const float* __restrict__ W2, const float* __restrict__ b2)
{
    __shared__ float  xs[64][129];      // input rows, pad 129 -> conflict-free column reads
    __shared__ float4 ws[16][32];       // W chunk: 16 c-rows x 128 f (as 32 float4)

    const int which = blockIdx.y;
    const float* in   = which ? y  : x;
    const float* W    = which ? W2 : W1;
    const float* bias = which ? b2 : b1;
    float* out        = which ? g_yk : g_xq;

    const int base = blockIdx.x * 64;   // pixel row base in [0, B*HW)
    const int t    = threadIdx.x;
    const int row  = t & 63;            // warp = 32 consecutive rows, same fgrp
    const int fgrp = t >> 6;            // 0..3
    const int f0   = fgrp * 32;

    // Load 64x128 input rows (coalesced float4).
    for (int v = t; v < 64 * 32; v += 256) {
        int r = v >> 5, c4 = v & 31;
        float4 d = reinterpret_cast<const float4*>(in + (long)(base + r) * kC)[c4];
        xs[r][c4 * 4 + 0] = d.x; xs[r][c4 * 4 + 1] = d.y;
        xs[r][c4 * 4 + 2] = d.z; xs[r][c4 * 4 + 3] = d.w;
    }

    float acc[32];
    #pragma unroll
    for (int i = 0; i < 32; i++) acc[i] = bias[f0 + i];

    for (int c0 = 0; c0 < kC; c0 += 16) {
        __syncthreads();   // guards xs (first iter) and ws rewrite (later iters)
        for (int v = t; v < 16 * 32; v += 256) {
            int r = v >> 5, c4 = v & 31;
            ws[r][c4] = reinterpret_cast<const float4*>(W + (long)(c0 + r) * kNF)[c4];
        }
        __syncthreads();
        #pragma unroll
        for (int cc = 0; cc < 16; cc++) {
            float xv = xs[row][c0 + cc];
            #pragma unroll
            for (int q = 0; q < 8; q++) {
                float4 w = ws[cc][fgrp * 8 + q];   // same addr across warp -> broadcast
                acc[q * 4 + 0] += xv * w.x;
                acc[q * 4 + 1] += xv * w.y;
                acc[q * 4 + 2] += xv * w.z;
                acc[q * 4 + 3] += xv * w.w;
            }
        }
    }

    float* o = out + (long)(base + row) * kNF + f0;
    #pragma unroll
    for (int q = 0; q < 8; q++) {
        float4 d = make_float4(acc[q * 4 + 0], acc[q * 4 + 1],
                               acc[q * 4 + 2], acc[q * 4 + 3]);
        reinterpret_cast<float4*>(o)[q] = d;
    }
}

// ---------------------------------------------------------------------------
// Attention: per CTA one 64-row query tile (yk_i), stream 64-wide j tiles.
//   S[m][j] = sum_c yki[m][c] * xqj[j][c]   -> sigmoid -> A
//   O[m][n] += sum_k A[m][k] * ykj[k][n]
// Thread grid 16x16: m = ty*4+i (4 rows), j = tx+16u (4 cols, strided),
// PV cols n = tx*4+e and 64+tx*4+e (8 cols). O register-resident (32/thread).
// grid = (64 i-tiles, 4 batches), block = 256, occupancy 2 -> 1 full wave.
// ---------------------------------------------------------------------------
__global__ __launch_bounds__(256, 2) void attn_kernel(float* __restrict__ out)
{
    extern __shared__ float smem[];
    float* s_yki = smem;                 // [64][RS]
    float* s_xqj = smem + 64 * RS;       // [64][RS]; recycled as A [64][AS]
    float* s_ykj = smem + 2 * 64 * RS;   // [64][RS]

    const int b  = blockIdx.y;
    const int i0 = blockIdx.x * 64;
    const int t  = threadIdx.x;
    const int ty = t >> 4;               // 0..15
    const int tx = t & 15;               // 0..15
    const long bbase = (long)b * kHW * kNF;

    // Load resident query tile yk_i.
    for (int v = t; v < 64 * 32; v += 256) {
        int r = v >> 5, c4 = v & 31;
        float4 d = reinterpret_cast<const float4*>(g_yk + bbase + (long)(i0 + r) * kNF)[c4];
        *reinterpret_cast<float4*>(&s_yki[r * RS + c4 * 4]) = d;
    }

    float O[4][8];
    #pragma unroll
    for (int i = 0; i < 4; i++)
        #pragma unroll
        for (int n = 0; n < 8; n++) O[i][n] = 0.f;

    for (int j0 = 0; j0 < kHW; j0 += 64) {
        __syncthreads();   // previous PV reads of A/ykj done (also guards yki load, iter 0)

        for (int v = t; v < 64 * 32; v += 256) {
            int r = v >> 5, c4 = v & 31;
            *reinterpret_cast<float4*>(&s_xqj[r * RS + c4 * 4]) =
                reinterpret_cast<const float4*>(g_xq + bbase + (long)(j0 + r) * kNF)[c4];
            *reinterpret_cast<float4*>(&s_ykj[r * RS + c4 * 4]) =
                reinterpret_cast<const float4*>(g_yk + bbase + (long)(j0 + r) * kNF)[c4];
        }
        __syncthreads();

        // ---- S = yki @ xqj^T ----
        float S[4][4];
        #pragma unroll
        for (int i = 0; i < 4; i++)
            #pragma unroll
            for (int u = 0; u < 4; u++) S[i][u] = 0.f;

        #pragma unroll 1
        for (int c4 = 0; c4 < 32; c4++) {
            float4 a[4], q[4];
            #pragma unroll
            for (int i = 0; i < 4; i++)
                a[i] = *reinterpret_cast<const float4*>(&s_yki[(ty * 4 + i) * RS + c4 * 4]);
            #pragma unroll
            for (int u = 0; u < 4; u++)
                q[u] = *reinterpret_cast<const float4*>(&s_xqj[(tx + 16 * u) * RS + c4 * 4]);
            #pragma unroll
            for (int i = 0; i < 4; i++)
                #pragma unroll
                for (int u = 0; u < 4; u++) {
                    S[i][u] += a[i].x * q[u].x;
                    S[i][u] += a[i].y * q[u].y;
                    S[i][u] += a[i].z * q[u].z;
                    S[i][u] += a[i].w * q[u].w;
                }
        }
        __syncthreads();   // all reads of xqj done before recycling it for A

        // ---- sigmoid, stage A in recycled xqj buffer ----
        #pragma unroll
        for (int i = 0; i < 4; i++)
            #pragma unroll
            for (int u = 0; u < 4; u++) {
                float aval = __fdividef(1.f, 1.f + __expf(-S[i][u]));
                s_xqj[(ty * 4 + i) * AS + (tx + 16 * u)] = aval;
            }
        __syncthreads();

        // ---- O += A @ ykj ----
        #pragma unroll 4
        for (int k = 0; k < 64; k++) {
            float av[4];
            #pragma unroll
            for (int i = 0; i < 4; i++)
                av[i] = s_xqj[(ty * 4 + i) * AS + k];   // broadcast across tx
            float4 w0 = *reinterpret_cast<const float4*>(&s_ykj[k * RS + tx * 4]);
            float4 w1 = *reinterpret_cast<const float4*>(&s_ykj[k * RS + 64 + tx * 4]);
            #pragma unroll
            for (int i = 0; i < 4; i++) {
                O[i][0] += av[i] * w0.x;  O[i][1] += av[i] * w0.y;
                O[i][2] += av[i] * w0.z;  O[i][3] += av[i] * w0.w;
                O[i][4] += av[i] * w1.x;  O[i][5] += av[i] * w1.y;
                O[i][6] += av[i] * w1.z;  O[i][7] += av[i] * w1.w;
            }
        }
    }

    // ---- epilogue: out = O + XQ ----
    #pragma unroll
    for (int i = 0; i < 4; i++) {
        long rowoff = bbase + (long)(i0 + ty * 4 + i) * kNF;
        float4 q0 = *reinterpret_cast<const float4*>(g_xq + rowoff + tx * 4);
        float4 q1 = *reinterpret_cast<const float4*>(g_xq + rowoff + 64 + tx * 4);
        float4 r0 = make_float4(O[i][0] + q0.x, O[i][1] + q0.y,
                                O[i][2] + q0.z, O[i][3] + q0.w);
        float4 r1 = make_float4(O[i][4] + q1.x, O[i][5] + q1.y,
                                O[i][6] + q1.z, O[i][7] + q1.w);
        *reinterpret_cast<float4*>(out + rowoff + tx * 4) = r0;
        *reinterpret_cast<float4*>(out + rowoff + 64 + tx * 4) = r1;
    }
}

// ---------------------------------------------------------------------------
extern "C" void kernel_launch(void* const* d_in, const int* in_sizes, int n_in,
                              void* d_out, int out_size)
{
    const float* x  = (const float*)d_in[0];
    const float* y  = (const float*)d_in[1];
    const float* W1 = (const float*)d_in[2];
    const float* b1 = (const float*)d_in[3];
    const float* W2 = (const float*)d_in[4];
    const float* b2 = (const float*)d_in[5];

    cudaFuncSetAttribute(attn_kernel, cudaFuncAttributeMaxDynamicSharedMemorySize,
                         ATTN_SMEM_BYTES);

    proj_kernel<<<dim3(256, 2), 256>>>(x, y, W1, b1, W2, b2);
    attn_kernel<<<dim3(64, 4), 256, ATTN_SMEM_BYTES>>>((float*)d_out);
}

// round 6
// speedup vs baseline: 2.8898x; 2.8809x over previous
#include <cuda_runtime.h>
#include <cuda_bf16.h>
#include <cstdint>

// ============================================================================
// out = sigmoid(YK @ XQ^T) @ YK + XQ ;  XQ = x@W1+b1, YK = y@W2+b2
// B=4, HW=4096, C=NF=128 fp32.
// sm_100 base target: tcgen05 unavailable -> warp-level mma.sync (HMMA) with
// bf16 hi/lo split (hh + hl + lh), FlashAttention-2 style fragment reuse.
// R6 fix: XQ j-tile loader covered only half the row (k<2,>>3,&7) -> NaN from
// uninitialized smem. Now k<4,>>4,&15 (full 256 B/row).
// ============================================================================

constexpr int kB = 4, kHW = 4096, kC = 128;
constexpr int TJ = 64, NJ = kHW / TJ;     // 64-wide j tiles

// smem strides in b32 units (bank = 4*(lane/4)+(lane%4) -> conflict-free)
constexpr int XQ_STR = 68;   // 136 bf16 per row (128 + 8 pad)
constexpr int YT_STR = 36;   // 72 bf16 per row (64 + 8 pad)

// smem byte layout: two j-tile buffers + resident YKi_lo
constexpr int XQH_OFF = 0;                      // 64 x 68 b32 = 17408 B
constexpr int XQL_OFF = 17408;
constexpr int YTH_OFF = 34816;                  // 128 x 36 b32 = 18432 B
constexpr int YTL_OFF = 53248;
constexpr int BUF_BYTES = 71680;
constexpr int YKIL_OFF = 2 * BUF_BYTES;         // 128 x 68 b32 = 34816 B
constexpr int SMEM_TOTAL = YKIL_OFF + 34816;    // 178176 B

// global scratch (allocation-free rule)
__device__ float          g_xq  [kB*kHW*kC];
__device__ unsigned short g_xq_h[kB*kHW*kC], g_xq_l[kB*kHW*kC];
__device__ unsigned short g_yk_h[kB*kHW*kC], g_yk_l[kB*kHW*kC];
__device__ unsigned short g_yt_h[kB*kHW*kC], g_yt_l[kB*kHW*kC];  // [b][feat][pix]

// ---------------------------------------------------------------------------
__device__ __forceinline__ uint32_t smem_u32(const void* p) {
    uint32_t a;
    asm("{ .reg .u64 t; cvta.to.shared.u64 t, %1; cvt.u32.u64 %0, t; }" : "=r"(a) : "l"(p));
    return a;
}
#define CP16(sm_addr, g_ptr) \
    asm volatile("cp.async.cg.shared.global [%0], [%1], 16;" \
        :: "r"(sm_addr), "l"(__cvta_generic_to_global(g_ptr)) : "memory")
#define CP_COMMIT() asm volatile("cp.async.commit_group;" ::: "memory")
#define CP_WAIT0()  asm volatile("cp.async.wait_group 0;" ::: "memory")

// D += A(4xb32 bf16) * B(2xb32 bf16), m16n8k16 row.col, fp32 accum
__device__ __forceinline__ void mma_bf16(float* d, const uint32_t* a,
                                         uint32_t b0, uint32_t b1) {
    asm volatile(
        "mma.sync.aligned.m16n8k16.row.col.f32.bf16.bf16.f32 "
        "{%0,%1,%2,%3}, {%4,%5,%6,%7}, {%8,%9}, {%0,%1,%2,%3};"
        : "+f"(d[0]), "+f"(d[1]), "+f"(d[2]), "+f"(d[3])
        : "r"(a[0]), "r"(a[1]), "r"(a[2]), "r"(a[3]), "r"(b0), "r"(b1));
}

// split pair (a0,a1) -> packed bf16x2 hi and lo-residual
__device__ __forceinline__ void packHL(float a0, float a1, uint32_t& hi, uint32_t& lo) {
    __nv_bfloat16 h0 = __float2bfloat16(a0), h1 = __float2bfloat16(a1);
    float l0 = a0 - __bfloat162float(h0);
    float l1 = a1 - __bfloat162float(h1);
    hi = (uint32_t)__bfloat16_as_ushort(h0) | ((uint32_t)__bfloat16_as_ushort(h1) << 16);
    asm("cvt.rn.bf16x2.f32 %0, %1, %2;" : "=r"(lo) : "f"(l1), "f"(l0));
}

// ---------------------------------------------------------------------------
// Projection: XQ/YK fp32 + bf16 hi/lo splits, plus transposed YK (g_yt).
// grid (256, 2), block 256.
// ---------------------------------------------------------------------------
__global__ __launch_bounds__(256) void proj_kernel(
    const float* __restrict__ x,  const float* __restrict__ y,
    const float* __restrict__ W1, const float* __restrict__ b1,
    const float* __restrict__ W2, const float* __restrict__ b2)
{
    __shared__ float  xs[64][129];
    __shared__ float4 ws[16][32];

    const int which = blockIdx.y;
    const float* in   = which ? y  : x;
    const float* W    = which ? W2 : W1;
    const float* bias = which ? b2 : b1;

    const int base = blockIdx.x * 64;
    const int t = threadIdx.x, row = t & 63, fgrp = t >> 6, f0 = fgrp * 32;

    for (int v = t; v < 64*32; v += 256) {
        int r = v >> 5, c4 = v & 31;
        float4 d = reinterpret_cast<const float4*>(in + (long)(base + r)*kC)[c4];
        xs[r][c4*4+0]=d.x; xs[r][c4*4+1]=d.y; xs[r][c4*4+2]=d.z; xs[r][c4*4+3]=d.w;
    }
    float acc[32];
    #pragma unroll
    for (int i = 0; i < 32; i++) acc[i] = bias[f0 + i];

    for (int c0 = 0; c0 < kC; c0 += 16) {
        __syncthreads();
        for (int v = t; v < 16*32; v += 256) {
            int r = v >> 5, c4 = v & 31;
            ws[r][c4] = reinterpret_cast<const float4*>(W + (long)(c0 + r)*kC)[c4];
        }
        __syncthreads();
        #pragma unroll
        for (int cc = 0; cc < 16; cc++) {
            float xv = xs[row][c0 + cc];
            #pragma unroll
            for (int q = 0; q < 8; q++) {
                float4 w = ws[cc][fgrp*8 + q];
                acc[q*4+0] += xv*w.x; acc[q*4+1] += xv*w.y;
                acc[q*4+2] += xv*w.z; acc[q*4+3] += xv*w.w;
            }
        }
    }

    const int prow = base + row;
    unsigned short hs[32], ls[32];
    #pragma unroll
    for (int i = 0; i < 32; i++) {
        float v = acc[i];
        __nv_bfloat16 h = __float2bfloat16(v);
        float lf = v - __bfloat162float(h);
        hs[i] = __bfloat16_as_ushort(h);
        ls[i] = __bfloat16_as_ushort(__float2bfloat16(lf));
    }
    unsigned hw_[16], lw_[16];
    #pragma unroll
    for (int k = 0; k < 16; k++) {
        hw_[k] = (unsigned)hs[2*k] | ((unsigned)hs[2*k+1] << 16);
        lw_[k] = (unsigned)ls[2*k] | ((unsigned)ls[2*k+1] << 16);
    }
    const int u4base = prow * 16 + fgrp * 4;

    if (which == 0) {
        float* o = g_xq + (long)prow*kC + f0;
        #pragma unroll
        for (int q = 0; q < 8; q++)
            reinterpret_cast<float4*>(o)[q] =
                make_float4(acc[q*4+0], acc[q*4+1], acc[q*4+2], acc[q*4+3]);
        #pragma unroll
        for (int q = 0; q < 4; q++) {
            reinterpret_cast<uint4*>(g_xq_h)[u4base+q] = make_uint4(hw_[4*q],hw_[4*q+1],hw_[4*q+2],hw_[4*q+3]);
            reinterpret_cast<uint4*>(g_xq_l)[u4base+q] = make_uint4(lw_[4*q],lw_[4*q+1],lw_[4*q+2],lw_[4*q+3]);
        }
    } else {
        #pragma unroll
        for (int q = 0; q < 4; q++) {
            reinterpret_cast<uint4*>(g_yk_h)[u4base+q] = make_uint4(hw_[4*q],hw_[4*q+1],hw_[4*q+2],hw_[4*q+3]);
            reinterpret_cast<uint4*>(g_yk_l)[u4base+q] = make_uint4(lw_[4*q],lw_[4*q+1],lw_[4*q+2],lw_[4*q+3]);
        }
        const int bb = prow >> 12, pb = prow & 4095;
        #pragma unroll
        for (int i = 0; i < 32; i++) {            // coalesced: lanes = consecutive pb
            int idx = (bb*kC + f0 + i)*kHW + pb;
            g_yt_h[idx] = hs[i];
            g_yt_l[idx] = ls[i];
        }
    }
}

// ---------------------------------------------------------------------------
// j-tile loader: XQ hi/lo [64 x 128] + YT hi/lo [128 x 64] via cp.async
// ---------------------------------------------------------------------------
__device__ __forceinline__ void load_jtile(uint32_t su, int buf, long pix0,
                                           int bIdx, int j0, int tid) {
    const uint32_t base = su + buf * BUF_BYTES;
    #pragma unroll
    for (int k = 0; k < 4; k++) {                 // XQ: 1024 chunks each (FIXED)
        int idx = tid + k*256, row = idx >> 4, q = idx & 15;
        const unsigned short* gh = g_xq_h + (pix0 + j0 + row)*kC + q*8;
        const unsigned short* gl = g_xq_l + (pix0 + j0 + row)*kC + q*8;
        CP16(base + XQH_OFF + row*272 + q*16, gh);
        CP16(base + XQL_OFF + row*272 + q*16, gl);
    }
    const long ytb = (long)bIdx * kC * kHW + j0;
    #pragma unroll
    for (int k = 0; k < 4; k++) {                 // YT: 1024 chunks each
        int idx = tid + k*256, row = idx >> 3, q = idx & 7;
        CP16(base + YTH_OFF + row*144 + q*16, g_yt_h + ytb + (long)row*kHW + q*8);
        CP16(base + YTL_OFF + row*144 + q*16, g_yt_l + ytb + (long)row*kHW + q*8);
    }
}

// ---------------------------------------------------------------------------
// Attention: grid (32 i-tiles, 4 batches), block 256 (8 warps x 16 rows)
// ---------------------------------------------------------------------------
__global__ __launch_bounds__(256) void attn_mma(float* __restrict__ out)
{
    extern __shared__ char smem[];
    const uint32_t su = smem_u32(smem);
    uint32_t* s32 = reinterpret_cast<uint32_t*>(smem);
    const int tid = threadIdx.x, w = tid >> 5, lane = tid & 31;
    const int r0 = lane >> 2, qd = lane & 3;
    const int b = blockIdx.y, i0 = blockIdx.x * 128;
    const long pix0 = (long)b * kHW;

    // prologue: j-tile 0 + resident YKi_lo via cp.async
    load_jtile(su, 0, pix0, b, 0, tid);
    #pragma unroll
    for (int k = 0; k < 8; k++) {                 // YKi_lo: 2048 chunks
        int idx = tid + k*256, row = idx >> 4, q = idx & 15;
        CP16(su + YKIL_OFF + row*272 + q*16, g_yk_l + (pix0 + i0 + row)*kC + q*8);
    }
    CP_COMMIT();

    // YKi_hi A-fragments straight from gmem (one-time)
    uint32_t aH[8][4];
    const unsigned short* ykb = g_yk_h + (pix0 + i0 + w*16) * kC;
    #pragma unroll
    for (int kb = 0; kb < 8; kb++) {
        int c0 = kb*16 + 2*qd;
        aH[kb][0] = *reinterpret_cast<const uint32_t*>(ykb +  r0      *kC + c0);
        aH[kb][1] = *reinterpret_cast<const uint32_t*>(ykb + (r0 + 8) *kC + c0);
        aH[kb][2] = *reinterpret_cast<const uint32_t*>(ykb +  r0      *kC + c0 + 8);
        aH[kb][3] = *reinterpret_cast<const uint32_t*>(ykb + (r0 + 8) *kC + c0 + 8);
    }

    float O[16][4];
    #pragma unroll
    for (int nt = 0; nt < 16; nt++)
        #pragma unroll
        for (int e = 0; e < 4; e++) O[nt][e] = 0.f;

    const uint32_t ykl = (YKIL_OFF >> 2) + (w*16) * XQ_STR;

    for (int j = 0; j < NJ; j++) {
        const int buf = j & 1;
        CP_WAIT0();
        __syncthreads();
        if (j + 1 < NJ) {
            load_jtile(su, buf ^ 1, pix0, b, (j + 1) * TJ, tid);
            CP_COMMIT();
        }

        const uint32_t bb  = (uint32_t)(buf * BUF_BYTES) >> 2;
        const uint32_t xqh = bb + (XQH_OFF >> 2), xql = bb + (XQL_OFF >> 2);

        // ---- S = YKi @ XQj^T (hh + hl + lh) ----
        float S[8][4];
        #pragma unroll
        for (int nt = 0; nt < 8; nt++)
            #pragma unroll
            for (int e = 0; e < 4; e++) S[nt][e] = 0.f;

        #pragma unroll
        for (int kb = 0; kb < 8; kb++) {
            uint32_t aL[4];
            const uint32_t ai = ykl + r0*XQ_STR + kb*8 + qd;
            aL[0] = s32[ai];
            aL[1] = s32[ai + 8*XQ_STR];
            aL[2] = s32[ai + 4];
            aL[3] = s32[ai + 8*XQ_STR + 4];
            #pragma unroll
            for (int nt = 0; nt < 8; nt++) {
                const uint32_t bi = (uint32_t)(8*nt + r0)*XQ_STR + kb*8 + qd;
                uint32_t bh0 = s32[xqh + bi], bh1 = s32[xqh + bi + 4];
                uint32_t bl0 = s32[xql + bi], bl1 = s32[xql + bi + 4];
                mma_bf16(S[nt], aH[kb], bh0, bh1);
                mma_bf16(S[nt], aH[kb], bl0, bl1);
                mma_bf16(S[nt], aL,     bh0, bh1);
            }
        }

        // ---- sigmoid (exact: EX2 + RCP) ----
        #pragma unroll
        for (int nt = 0; nt < 8; nt++)
            #pragma unroll
            for (int e = 0; e < 4; e++) {
                float ev = __expf(-S[nt][e]);
                S[nt][e] = __fdividef(1.f, 1.f + ev);
            }

        // ---- pack A-fragments: accumulator layout == A-operand layout ----
        uint32_t aPh[4][4], aPl[4][4];
        #pragma unroll
        for (int kb = 0; kb < 4; kb++) {
            packHL(S[2*kb  ][0], S[2*kb  ][1], aPh[kb][0], aPl[kb][0]);
            packHL(S[2*kb  ][2], S[2*kb  ][3], aPh[kb][1], aPl[kb][1]);
            packHL(S[2*kb+1][0], S[2*kb+1][1], aPh[kb][2], aPl[kb][2]);
            packHL(S[2*kb+1][2], S[2*kb+1][3], aPh[kb][3], aPl[kb][3]);
        }

        // ---- O += A @ YKj (hh + hl + lh), B from transposed-YK tile ----
        const uint32_t yth = bb + (YTH_OFF >> 2), ytl = bb + (YTL_OFF >> 2);
        #pragma unroll
        for (int nt = 0; nt < 16; nt++) {
            #pragma unroll
            for (int kb = 0; kb < 4; kb++) {
                const uint32_t bi = (uint32_t)(8*nt + r0)*YT_STR + kb*8 + qd;
                uint32_t bh0 = s32[yth + bi], bh1 = s32[yth + bi + 4];
                uint32_t bl0 = s32[ytl + bi], bl1 = s32[ytl + bi + 4];
                mma_bf16(O[nt], aPh[kb], bh0, bh1);
                mma_bf16(O[nt], aPh[kb], bl0, bl1);
                mma_bf16(O[nt], aPl[kb], bh0, bh1);
            }
        }
    }

    // ---- epilogue: out = O + XQ (fp32 residual) ----
    const long rowbase = pix0 + i0 + w*16;
    #pragma unroll
    for (int nt = 0; nt < 16; nt++) {
        const int c = 8*nt + 2*qd;
        const long o0 = (rowbase + r0    ) * kC + c;
        const long o1 = (rowbase + r0 + 8) * kC + c;
        float2 q0 = *reinterpret_cast<const float2*>(g_xq + o0);
        float2 q1 = *reinterpret_cast<const float2*>(g_xq + o1);
        *reinterpret_cast<float2*>(out + o0) = make_float2(O[nt][0] + q0.x, O[nt][1] + q0.y);
        *reinterpret_cast<float2*>(out + o1) = make_float2(O[nt][2] + q1.x, O[nt][3] + q1.y);
    }
}

// ---------------------------------------------------------------------------
extern "C" void kernel_launch(void* const* d_in, const int* in_sizes, int n_in,
                              void* d_out, int out_size)
{
    const float* x  = (const float*)d_in[0];
    const float* y  = (const float*)d_in[1];
    const float* W1 = (const float*)d_in[2];
    const float* b1 = (const float*)d_in[3];
    const float* W2 = (const float*)d_in[4];
    const float* b2 = (const float*)d_in[5];

    cudaFuncSetAttribute(attn_mma, cudaFuncAttributeMaxDynamicSharedMemorySize, SMEM_TOTAL);

    proj_kernel<<<dim3(256, 2), 256>>>(x, y, W1, b1, W2, b2);
    attn_mma<<<dim3(32, 4), 256, SMEM_TOTAL>>>((float*)d_out);
}